// round 4
// baseline (speedup 1.0000x reference)
#include <cuda_runtime.h>
#include <cuda_bf16.h>
#include <math_constants.h>

#define NN 50000
#define EE 1600000
#define FIN 256
#define HEADS 4
#define OUTF 32
#define HO 128          // HEADS*OUTF
#define NEG_SLOPE 0.2f

// ---------------- scratch (static device globals; 16B-aligned) -------------
__device__ __align__(16) float g_ft[NN * HO];     // projected features  [N,128]
__device__ __align__(16) float g_el[NN * HEADS];  // left attn logits    [N,4]
__device__ __align__(16) float g_er[NN * HEADS];  // right attn logits   [N,4]
__device__ __align__(16) float g_m [NN * HEADS];  // segment max         [N,4]
__device__ __align__(16) float g_s [NN * HEADS];  // segment sum         [N,4]
__device__ __align__(16) float g_e [EE * HEADS];  // per-edge logits/exp [E,4]
__device__ int g_is64;                            // 1 if indices are int64

// ---------------- helpers --------------------------------------------------
__device__ __forceinline__ int load_idx(const void* p, int i, int is64, int n) {
    int v;
    if (is64) v = (int)((const long long*)p)[i];
    else      v = ((const int*)p)[i];
    // clamp: no-op when detection is right; turns a crash into a measurable
    // wrong answer (with profile) if it is ever wrong.
    v = v < 0 ? 0 : v;
    return v >= n ? n - 1 : v;
}

__device__ __forceinline__ void red_add_v4(float* addr, float4 v) {
    asm volatile("red.global.add.v4.f32 [%0], {%1,%2,%3,%4};"
                 :: "l"(addr), "f"(v.x), "f"(v.y), "f"(v.z), "f"(v.w)
                 : "memory");
}

__device__ __forceinline__ void atomic_max_f(float* addr, float v) {
    float cur = *((volatile float*)addr);
    if (v <= cur) return;
    if (v >= 0.0f) atomicMax((int*)addr, __float_as_int(v));
    else           atomicMin((unsigned int*)addr, __float_as_uint(v));
}

// ---------------- kernel D: detect index dtype -----------------------------
// If indices are int64 with values < 2^31, every odd 32-bit word is 0.
// If int32, odd words are random indices in [0,50000): OR over 4096 of them
// is nonzero with probability 1 - 2^-something astronomical.
__global__ void k_detect(const unsigned int* __restrict__ idx_words) {
    unsigned int acc = 0;
#pragma unroll 8
    for (int i = 1; i < 8192; i += 2) acc |= idx_words[i];
    g_is64 = (acc == 0u) ? 1 : 0;
}

// ---------------- kernel 0: init out / m / s -------------------------------
__global__ void k_init(float* __restrict__ out, int n_out, int n_ms) {
    int i = blockIdx.x * blockDim.x + threadIdx.x;
    if (i < n_out) out[i] = 0.0f;
    if (i < n_ms) {
        g_m[i] = -CUDART_INF_F;
        g_s[i] = 0.0f;
    }
}

// ---------------- kernel 1: ft = feat @ W^T  (fp32 SIMT tiled GEMM) --------
// M=50000, N=128, K=256.  Tile 64x128, BK=32, 256 threads, 4x8 per thread.
#define GM_BM 64
#define GM_BN 128
#define GM_BK 32
__global__ __launch_bounds__(256) void k_gemm(const float* __restrict__ feat,
                                              const float* __restrict__ W,
                                              int n_nodes) {
    __shared__ float As[GM_BK][GM_BM + 1];
    __shared__ float Bs[GM_BK][GM_BN + 4];

    const int tid = threadIdx.x;
    const int tx  = tid & 15;
    const int ty  = tid >> 4;
    const int row0 = blockIdx.x * GM_BM;

    float acc[4][8];
#pragma unroll
    for (int i = 0; i < 4; i++)
#pragma unroll
        for (int j = 0; j < 8; j++) acc[i][j] = 0.0f;

    for (int k0 = 0; k0 < FIN; k0 += GM_BK) {
#pragma unroll
        for (int l = 0; l < 2; l++) {
            int idx = l * 256 + tid;
            int r   = idx >> 3;
            int kk  = (idx & 7) * 4;
            float4 v = make_float4(0.f, 0.f, 0.f, 0.f);
            if (row0 + r < n_nodes)
                v = *(const float4*)&feat[(size_t)(row0 + r) * FIN + k0 + kk];
            As[kk + 0][r] = v.x; As[kk + 1][r] = v.y;
            As[kk + 2][r] = v.z; As[kk + 3][r] = v.w;
        }
#pragma unroll
        for (int l = 0; l < 4; l++) {
            int idx = l * 256 + tid;
            int r   = idx >> 3;
            int kk  = (idx & 7) * 4;
            float4 v = *(const float4*)&W[(size_t)r * FIN + k0 + kk];
            Bs[kk + 0][r] = v.x; Bs[kk + 1][r] = v.y;
            Bs[kk + 2][r] = v.z; Bs[kk + 3][r] = v.w;
        }
        __syncthreads();

#pragma unroll
        for (int k = 0; k < GM_BK; k++) {
            float a[4];
#pragma unroll
            for (int i = 0; i < 4; i++) a[i] = As[k][ty * 4 + i];
            float4 b0 = *(const float4*)&Bs[k][tx * 8];
            float4 b1 = *(const float4*)&Bs[k][tx * 8 + 4];
            float b[8] = {b0.x, b0.y, b0.z, b0.w, b1.x, b1.y, b1.z, b1.w};
#pragma unroll
            for (int i = 0; i < 4; i++)
#pragma unroll
                for (int j = 0; j < 8; j++) acc[i][j] += a[i] * b[j];
        }
        __syncthreads();
    }

#pragma unroll
    for (int i = 0; i < 4; i++) {
        int r = row0 + ty * 4 + i;
        if (r < n_nodes) {
            float4 v0 = make_float4(acc[i][0], acc[i][1], acc[i][2], acc[i][3]);
            float4 v1 = make_float4(acc[i][4], acc[i][5], acc[i][6], acc[i][7]);
            *(float4*)&g_ft[(size_t)r * HO + tx * 8]     = v0;
            *(float4*)&g_ft[(size_t)r * HO + tx * 8 + 4] = v1;
        }
    }
}

// ---------------- kernel 2: el/er per node (warp per node) -----------------
__global__ __launch_bounds__(256) void k_attn_dot(const float* __restrict__ attn,
                                                  int n_nodes) {
    int warp = (blockIdx.x * blockDim.x + threadIdx.x) >> 5;
    int lane = threadIdx.x & 31;
    if (warp >= n_nodes) return;

    float4 f = ((const float4*)g_ft)[(size_t)warp * 32 + lane];
    int h   = lane >> 3;
    int off = (lane & 7) * 4;
    float4 al = *(const float4*)&attn[h * 64 + off];
    float4 ar = *(const float4*)&attn[h * 64 + 32 + off];
    float dl = f.x * al.x + f.y * al.y + f.z * al.z + f.w * al.w;
    float dr = f.x * ar.x + f.y * ar.y + f.z * ar.z + f.w * ar.w;
#pragma unroll
    for (int m = 4; m >= 1; m >>= 1) {
        dl += __shfl_xor_sync(0xffffffffu, dl, m);
        dr += __shfl_xor_sync(0xffffffffu, dr, m);
    }
    if ((lane & 7) == 0) {
        g_el[warp * HEADS + h] = dl;
        g_er[warp * HEADS + h] = dr;
    }
}

// ---------------- kernel 3: edge logits + segment max ----------------------
__global__ __launch_bounds__(256) void k_edge_logits(const void* __restrict__ src,
                                                     const void* __restrict__ dst,
                                                     int n_edges, int n_nodes) {
    int i = blockIdx.x * blockDim.x + threadIdx.x;
    if (i >= n_edges) return;
    int is64 = g_is64;
    int s = load_idx(src, i, is64, n_nodes);
    int d = load_idx(dst, i, is64, n_nodes);
    float4 a = ((const float4*)g_el)[s];
    float4 b = ((const float4*)g_er)[d];
    float4 e;
    e.x = a.x + b.x; e.y = a.y + b.y; e.z = a.z + b.z; e.w = a.w + b.w;
    e.x = e.x > 0.f ? e.x : NEG_SLOPE * e.x;
    e.y = e.y > 0.f ? e.y : NEG_SLOPE * e.y;
    e.z = e.z > 0.f ? e.z : NEG_SLOPE * e.z;
    e.w = e.w > 0.f ? e.w : NEG_SLOPE * e.w;
    ((float4*)g_e)[i] = e;
    float* mp = g_m + (size_t)d * HEADS;
    atomic_max_f(mp + 0, e.x);
    atomic_max_f(mp + 1, e.y);
    atomic_max_f(mp + 2, e.z);
    atomic_max_f(mp + 3, e.w);
}

// ---------------- kernel 4: exp + segment sum ------------------------------
__global__ __launch_bounds__(256) void k_edge_exp(const void* __restrict__ dst,
                                                  int n_edges, int n_nodes) {
    int i = blockIdx.x * blockDim.x + threadIdx.x;
    if (i >= n_edges) return;
    int d = load_idx(dst, i, g_is64, n_nodes);
    float4 e = ((const float4*)g_e)[i];
    float4 m = ((const float4*)g_m)[d];
    float4 ex;
    ex.x = __expf(e.x - m.x);
    ex.y = __expf(e.y - m.y);
    ex.z = __expf(e.z - m.z);
    ex.w = __expf(e.w - m.w);
    ((float4*)g_e)[i] = ex;
    red_add_v4(g_s + (size_t)d * HEADS, ex);
}

// ---------------- kernel 5: weighted message aggregation (warp per edge) ---
__global__ __launch_bounds__(256) void k_aggregate(const void* __restrict__ src,
                                                   const void* __restrict__ dst,
                                                   float* __restrict__ out,
                                                   int n_edges, int n_nodes) {
    int warp = (blockIdx.x * blockDim.x + threadIdx.x) >> 5;
    int lane = threadIdx.x & 31;
    if (warp >= n_edges) return;
    int is64 = g_is64;
    int s = load_idx(src, warp, is64, n_nodes);
    int d = load_idx(dst, warp, is64, n_nodes);
    int h = lane >> 3;
    float ex  = g_e[(size_t)warp * HEADS + h];
    float sum = g_s[(size_t)d * HEADS + h];
    float a = __fdividef(ex, sum);
    float4 f = ((const float4*)g_ft)[(size_t)s * 32 + lane];
    float4 v = make_float4(f.x * a, f.y * a, f.z * a, f.w * a);
    red_add_v4(out + (size_t)d * HO + lane * 4, v);
}

// ---------------- launch ---------------------------------------------------
extern "C" void kernel_launch(void* const* d_in, const int* in_sizes, int n_in,
                              void* d_out, int out_size) {
    const float* feat = (const float*)d_in[0];
    const void*  src  = d_in[1];
    const void*  dst  = d_in[2];
    const float* W    = (const float*)d_in[3];
    const float* attn = (const float*)d_in[4];
    float*       out  = (float*)d_out;

    const int n_nodes = in_sizes[0] / FIN;   // 50000
    const int n_edges = in_sizes[1];         // 1600000

    // D) detect index dtype (int32 vs int64)
    k_detect<<<1, 1>>>((const unsigned int*)src);
    // 0) init out / m / s
    k_init<<<(out_size + 255) / 256, 256>>>(out, out_size, n_nodes * HEADS);
    // 1) GEMM
    k_gemm<<<(n_nodes + GM_BM - 1) / GM_BM, 256>>>(feat, W, n_nodes);
    // 2) attention dots
    k_attn_dot<<<(n_nodes * 32 + 255) / 256, 256>>>(attn, n_nodes);
    // 3) edge logits + max
    k_edge_logits<<<(n_edges + 255) / 256, 256>>>(src, dst, n_edges, n_nodes);
    // 4) exp + sum
    k_edge_exp<<<(n_edges + 255) / 256, 256>>>(dst, n_edges, n_nodes);
    // 5) aggregate
    {
        long long threads = (long long)n_edges * 32;
        int blocks = (int)((threads + 255) / 256);
        k_aggregate<<<blocks, 256>>>(src, dst, out, n_edges, n_nodes);
    }
}

// round 5
// speedup vs baseline: 1.3509x; 1.3509x over previous
#include <cuda_runtime.h>
#include <cuda_bf16.h>
#include <math_constants.h>

#define NN 50000
#define EE 1600000
#define FIN 256
#define HEADS 4
#define OUTF 32
#define HO 128          // HEADS*OUTF
#define NEG_SLOPE 0.2f

// ---------------- scratch (static device globals; 16B-aligned) -------------
__device__ __align__(16) float g_ft[NN * HO];     // projected features  [N,128]
__device__ __align__(16) float g_el[NN * HEADS];  // left attn logits    [N,4]
__device__ __align__(16) float g_er[NN * HEADS];  // right attn logits   [N,4]
__device__ int g_deg   [NN];                      // in-degree histogram
__device__ int g_off   [NN + 1];                  // CSR offsets (by dst)
__device__ int g_cursor[NN];                      // scatter cursors
__device__ int g_perm  [EE];                      // edge ids sorted by dst
__device__ int g_is64;                            // 1 if indices are int64

// ---------------- helpers --------------------------------------------------
__device__ __forceinline__ int load_idx(const void* p, int i, int is64, int n) {
    int v;
    if (is64) v = (int)((const long long*)p)[i];
    else      v = ((const int*)p)[i];
    v = v < 0 ? 0 : v;
    return v >= n ? n - 1 : v;
}

// ---------------- kernel D: detect index dtype -----------------------------
__global__ void k_detect(const unsigned int* __restrict__ idx_words) {
    unsigned int acc = 0;
#pragma unroll 8
    for (int i = 1; i < 8192; i += 2) acc |= idx_words[i];
    g_is64 = (acc == 0u) ? 1 : 0;
}

// ---------------- kernel 0: zero degree histogram --------------------------
__global__ void k_zero_deg(int n_nodes) {
    int i = blockIdx.x * blockDim.x + threadIdx.x;
    if (i < n_nodes) g_deg[i] = 0;
}

// ---------------- kernel 1: ft = feat @ W^T  (fp32 SIMT tiled GEMM) --------
#define GM_BM 64
#define GM_BN 128
#define GM_BK 32
__global__ __launch_bounds__(256) void k_gemm(const float* __restrict__ feat,
                                              const float* __restrict__ W,
                                              int n_nodes) {
    __shared__ float As[GM_BK][GM_BM + 1];
    __shared__ float Bs[GM_BK][GM_BN + 4];

    const int tid = threadIdx.x;
    const int tx  = tid & 15;
    const int ty  = tid >> 4;
    const int row0 = blockIdx.x * GM_BM;

    float acc[4][8];
#pragma unroll
    for (int i = 0; i < 4; i++)
#pragma unroll
        for (int j = 0; j < 8; j++) acc[i][j] = 0.0f;

    for (int k0 = 0; k0 < FIN; k0 += GM_BK) {
#pragma unroll
        for (int l = 0; l < 2; l++) {
            int idx = l * 256 + tid;
            int r   = idx >> 3;
            int kk  = (idx & 7) * 4;
            float4 v = make_float4(0.f, 0.f, 0.f, 0.f);
            if (row0 + r < n_nodes)
                v = *(const float4*)&feat[(size_t)(row0 + r) * FIN + k0 + kk];
            As[kk + 0][r] = v.x; As[kk + 1][r] = v.y;
            As[kk + 2][r] = v.z; As[kk + 3][r] = v.w;
        }
#pragma unroll
        for (int l = 0; l < 4; l++) {
            int idx = l * 256 + tid;
            int r   = idx >> 3;
            int kk  = (idx & 7) * 4;
            float4 v = *(const float4*)&W[(size_t)r * FIN + k0 + kk];
            Bs[kk + 0][r] = v.x; Bs[kk + 1][r] = v.y;
            Bs[kk + 2][r] = v.z; Bs[kk + 3][r] = v.w;
        }
        __syncthreads();

#pragma unroll
        for (int k = 0; k < GM_BK; k++) {
            float a[4];
#pragma unroll
            for (int i = 0; i < 4; i++) a[i] = As[k][ty * 4 + i];
            float4 b0 = *(const float4*)&Bs[k][tx * 8];
            float4 b1 = *(const float4*)&Bs[k][tx * 8 + 4];
            float b[8] = {b0.x, b0.y, b0.z, b0.w, b1.x, b1.y, b1.z, b1.w};
#pragma unroll
            for (int i = 0; i < 4; i++)
#pragma unroll
                for (int j = 0; j < 8; j++) acc[i][j] += a[i] * b[j];
        }
        __syncthreads();
    }

#pragma unroll
    for (int i = 0; i < 4; i++) {
        int r = row0 + ty * 4 + i;
        if (r < n_nodes) {
            float4 v0 = make_float4(acc[i][0], acc[i][1], acc[i][2], acc[i][3]);
            float4 v1 = make_float4(acc[i][4], acc[i][5], acc[i][6], acc[i][7]);
            *(float4*)&g_ft[(size_t)r * HO + tx * 8]     = v0;
            *(float4*)&g_ft[(size_t)r * HO + tx * 8 + 4] = v1;
        }
    }
}

// ---------------- kernel 2: el/er per node (warp per node) -----------------
__global__ __launch_bounds__(256) void k_attn_dot(const float* __restrict__ attn,
                                                  int n_nodes) {
    int warp = (blockIdx.x * blockDim.x + threadIdx.x) >> 5;
    int lane = threadIdx.x & 31;
    if (warp >= n_nodes) return;

    float4 f = ((const float4*)g_ft)[(size_t)warp * 32 + lane];
    int h   = lane >> 3;
    int off = (lane & 7) * 4;
    float4 al = *(const float4*)&attn[h * 64 + off];
    float4 ar = *(const float4*)&attn[h * 64 + 32 + off];
    float dl = f.x * al.x + f.y * al.y + f.z * al.z + f.w * al.w;
    float dr = f.x * ar.x + f.y * ar.y + f.z * ar.z + f.w * ar.w;
#pragma unroll
    for (int m = 4; m >= 1; m >>= 1) {
        dl += __shfl_xor_sync(0xffffffffu, dl, m);
        dr += __shfl_xor_sync(0xffffffffu, dr, m);
    }
    if ((lane & 7) == 0) {
        g_el[warp * HEADS + h] = dl;
        g_er[warp * HEADS + h] = dr;
    }
}

// ---------------- kernel 3: degree histogram over dst ----------------------
__global__ __launch_bounds__(256) void k_hist(const void* __restrict__ dst,
                                              int n_edges, int n_nodes) {
    int i = blockIdx.x * blockDim.x + threadIdx.x;
    if (i >= n_edges) return;
    int d = load_idx(dst, i, g_is64, n_nodes);
    atomicAdd(&g_deg[d], 1);
}

// ---------------- kernel 4: single-block exclusive scan --------------------
__global__ __launch_bounds__(1024) void k_scan(int n) {
    __shared__ int wsum[32];
    const int tid  = threadIdx.x;
    const int lane = tid & 31;
    const int wid  = tid >> 5;
    const int per  = (n + 1023) >> 10;
    const int beg  = tid * per;
    const int end  = min(beg + per, n);

    int local = 0;
    for (int j = beg; j < end; j++) local += g_deg[j];

    // warp inclusive scan
    int v = local;
#pragma unroll
    for (int o = 1; o < 32; o <<= 1) {
        int t = __shfl_up_sync(0xffffffffu, v, o);
        if (lane >= o) v += t;
    }
    if (lane == 31) wsum[wid] = v;
    __syncthreads();
    if (wid == 0) {
        int s = wsum[lane];
#pragma unroll
        for (int o = 1; o < 32; o <<= 1) {
            int t = __shfl_up_sync(0xffffffffu, s, o);
            if (lane >= o) s += t;
        }
        wsum[lane] = s;   // inclusive scan of warp sums
    }
    __syncthreads();

    int pre = v - local + (wid > 0 ? wsum[wid - 1] : 0);  // exclusive prefix
    int run = pre;
    for (int j = beg; j < end; j++) {
        int d = g_deg[j];
        g_off[j]    = run;
        g_cursor[j] = run;
        run += d;
    }
    if (beg < n && end == n) g_off[n] = run;   // total
}

// ---------------- kernel 5: scatter edge ids into CSR ----------------------
__global__ __launch_bounds__(256) void k_scatter(const void* __restrict__ dst,
                                                 int n_edges, int n_nodes) {
    int i = blockIdx.x * blockDim.x + threadIdx.x;
    if (i >= n_edges) return;
    int d = load_idx(dst, i, g_is64, n_nodes);
    int pos = atomicAdd(&g_cursor[d], 1);
    g_perm[pos] = i;
}

// ---------------- kernel 6: fused softmax + aggregation (warp per node) ----
__global__ __launch_bounds__(256) void k_agg_csr(const void* __restrict__ src,
                                                 float* __restrict__ out,
                                                 int n_nodes) {
    int node = (blockIdx.x * blockDim.x + threadIdx.x) >> 5;
    int lane = threadIdx.x & 31;
    if (node >= n_nodes) return;

    const int is64 = g_is64;
    const int beg = g_off[node];
    const int end = g_off[node + 1];
    const int h   = lane >> 3;
    const float er_h = g_er[node * HEADS + h];

    float4 acc = make_float4(0.f, 0.f, 0.f, 0.f);
    float  sw  = 0.f;

    // software pipeline: prefetch edge id + src index one iteration ahead
    int e = (beg < end) ? g_perm[beg] : 0;
    int s = (beg < end) ? load_idx(src, e, is64, n_nodes) : 0;
    for (int j = beg; j < end; j++) {
        int s_cur = s;
        if (j + 1 < end) {
            int e_n = g_perm[j + 1];
            s = load_idx(src, e_n, is64, n_nodes);
        }
        float lg = g_el[s_cur * HEADS + h] + er_h;
        lg = lg > 0.f ? lg : NEG_SLOPE * lg;
        float w = __expf(lg);
        float4 f = ((const float4*)g_ft)[(size_t)s_cur * 32 + lane];
        acc.x += w * f.x; acc.y += w * f.y;
        acc.z += w * f.z; acc.w += w * f.w;
        sw += w;
    }

    float inv = sw > 0.f ? __fdividef(1.f, sw) : 0.f;
    ((float4*)out)[(size_t)node * 32 + lane] =
        make_float4(acc.x * inv, acc.y * inv, acc.z * inv, acc.w * inv);
}

// ---------------- launch ---------------------------------------------------
extern "C" void kernel_launch(void* const* d_in, const int* in_sizes, int n_in,
                              void* d_out, int out_size) {
    const float* feat = (const float*)d_in[0];
    const void*  src  = d_in[1];
    const void*  dst  = d_in[2];
    const float* W    = (const float*)d_in[3];
    const float* attn = (const float*)d_in[4];
    float*       out  = (float*)d_out;

    const int n_nodes = in_sizes[0] / FIN;   // 50000
    const int n_edges = in_sizes[1];         // 1600000

    // D) detect index dtype (int32 vs int64)
    k_detect<<<1, 1>>>((const unsigned int*)src);
    // 0) zero degree histogram (graph replays need fresh state)
    k_zero_deg<<<(n_nodes + 255) / 256, 256>>>(n_nodes);
    // 1) GEMM
    k_gemm<<<(n_nodes + GM_BM - 1) / GM_BM, 256>>>(feat, W, n_nodes);
    // 2) attention dots
    k_attn_dot<<<(n_nodes * 32 + 255) / 256, 256>>>(attn, n_nodes);
    // 3) CSR: histogram
    k_hist<<<(n_edges + 255) / 256, 256>>>(dst, n_edges, n_nodes);
    // 4) CSR: scan
    k_scan<<<1, 1024>>>(n_nodes);
    // 5) CSR: scatter
    k_scatter<<<(n_edges + 255) / 256, 256>>>(dst, n_edges, n_nodes);
    // 6) fused softmax + aggregation
    k_agg_csr<<<(n_nodes * 32 + 255) / 256, 256>>>(src, out, n_nodes);
}

// round 8
// speedup vs baseline: 1.6767x; 1.2412x over previous
#include <cuda_runtime.h>
#include <cuda_bf16.h>
#include <math_constants.h>

#define NN 50000
#define EE 1600000
#define FIN 256
#define HEADS 4
#define OUTF 32
#define HO 128          // HEADS*OUTF
#define NEG_SLOPE 0.2f

// ---------------- scratch (static device globals; 16B-aligned) -------------
__device__ __align__(16) float g_ft[NN * HO];     // projected features  [N,128]
__device__ __align__(16) float g_el[NN * HEADS];  // left attn logits    [N,4]
__device__ __align__(16) float g_er[NN * HEADS];  // right attn logits   [N,4]
__device__ int g_deg   [NN];                      // in-degree histogram
__device__ int g_off   [NN + 1];                  // CSR offsets (by dst)
__device__ int g_cursor[NN];                      // scatter cursors
__device__ int g_perm  [EE];                      // edge ids sorted by dst
__device__ int g_is64;                            // 1 if indices are int64

// ---------------- helpers --------------------------------------------------
__device__ __forceinline__ int load_idx(const void* p, int i, int is64, int n) {
    int v;
    if (is64) v = (int)((const long long*)p)[i];
    else      v = ((const int*)p)[i];
    v = v < 0 ? 0 : v;
    return v >= n ? n - 1 : v;
}

__device__ __forceinline__ unsigned tf32_hi(float x) {
    unsigned r;
    asm("cvt.rna.tf32.f32 %0, %1;" : "=r"(r) : "f"(x));
    return r;
}

__device__ __forceinline__ void mma_tf32(float c[4],
                                         unsigned a0, unsigned a1,
                                         unsigned a2, unsigned a3,
                                         unsigned b0, unsigned b1) {
    asm volatile(
        "mma.sync.aligned.m16n8k8.row.col.f32.tf32.tf32.f32 "
        "{%0,%1,%2,%3}, {%4,%5,%6,%7}, {%8,%9}, {%0,%1,%2,%3};"
        : "+f"(c[0]), "+f"(c[1]), "+f"(c[2]), "+f"(c[3])
        : "r"(a0), "r"(a1), "r"(a2), "r"(a3), "r"(b0), "r"(b1));
}

// ---------------- kernel D: detect index dtype + zero degree ---------------
__global__ void k_detect(const unsigned int* __restrict__ idx_words, int n_nodes) {
    int i = blockIdx.x * blockDim.x + threadIdx.x;
    if (i < n_nodes) g_deg[i] = 0;
    if (blockIdx.x == 0 && threadIdx.x == 0) {
        unsigned int acc = 0;
#pragma unroll 8
        for (int j = 1; j < 8192; j += 2) acc |= idx_words[j];
        g_is64 = (acc == 0u) ? 1 : 0;
    }
}

// ---------------- kernel 1: ft = feat @ W^T  (tf32 tensor, 3xTF32) ---------
// M=50000, N=128, K=256. Block tile 128x128, BK=32, 256 thr = 8 warps (4m x 2n).
// Warp tile 32(m) x 64(n): 2 m-tiles(16) x 8 n-tiles(8), m16n8k8 fragments.
#define TBM 128
#define TBK 32
__global__ __launch_bounds__(256) void k_gemm_tc(const float* __restrict__ feat,
                                                 const float* __restrict__ W,
                                                 int n_nodes) {
    __shared__ float As[TBM][TBK + 4];   // stride 36: conflict-free frag loads
    __shared__ float Bs[HO][TBK + 4];

    const int tid    = threadIdx.x;
    const int lane   = tid & 31;
    const int wid    = tid >> 5;
    const int warp_m = wid & 3;          // 0..3 -> 32 rows each
    const int warp_n = wid >> 2;         // 0..1 -> 64 cols each
    const int row0   = blockIdx.x * TBM;

    const int fr = lane >> 2;            // fragment row  (0..7)
    const int fc = lane & 3;             // fragment col  (0..3)

    float acc[2][8][4];
#pragma unroll
    for (int mt = 0; mt < 2; mt++)
#pragma unroll
        for (int nt = 0; nt < 8; nt++)
#pragma unroll
            for (int q = 0; q < 4; q++) acc[mt][nt][q] = 0.0f;

    for (int k0 = 0; k0 < FIN; k0 += TBK) {
        // stage A: 128 rows x 32 k = 1024 float4, 4 per thread
#pragma unroll
        for (int l = 0; l < 4; l++) {
            int idx = l * 256 + tid;
            int r   = idx >> 3;
            int kk  = (idx & 7) * 4;
            float4 v = make_float4(0.f, 0.f, 0.f, 0.f);
            if (row0 + r < n_nodes)
                v = *(const float4*)&feat[(size_t)(row0 + r) * FIN + k0 + kk];
            *(float4*)&As[r][kk] = v;
        }
        // stage B: 128 W-rows x 32 k
#pragma unroll
        for (int l = 0; l < 4; l++) {
            int idx = l * 256 + tid;
            int r   = idx >> 3;
            int kk  = (idx & 7) * 4;
            *(float4*)&Bs[r][kk] = *(const float4*)&W[(size_t)r * FIN + k0 + kk];
        }
        __syncthreads();

#pragma unroll
        for (int kk = 0; kk < TBK; kk += 8) {
            // A fragments (2 m-tiles), hi/lo split
            unsigned ah[2][4], al[2][4];
#pragma unroll
            for (int mt = 0; mt < 2; mt++) {
                int rb = warp_m * 32 + mt * 16;
                float a0 = As[rb + fr     ][kk + fc    ];
                float a1 = As[rb + fr + 8 ][kk + fc    ];
                float a2 = As[rb + fr     ][kk + fc + 4];
                float a3 = As[rb + fr + 8 ][kk + fc + 4];
                ah[mt][0] = tf32_hi(a0); al[mt][0] = __float_as_uint(a0 - __uint_as_float(ah[mt][0]));
                ah[mt][1] = tf32_hi(a1); al[mt][1] = __float_as_uint(a1 - __uint_as_float(ah[mt][1]));
                ah[mt][2] = tf32_hi(a2); al[mt][2] = __float_as_uint(a2 - __uint_as_float(ah[mt][2]));
                ah[mt][3] = tf32_hi(a3); al[mt][3] = __float_as_uint(a3 - __uint_as_float(ah[mt][3]));
            }
            // B fragments (8 n-tiles), hi/lo split; 3xTF32 accumulate
#pragma unroll
            for (int nt = 0; nt < 8; nt++) {
                int cb = warp_n * 64 + nt * 8;
                float b0 = Bs[cb + fr][kk + fc    ];
                float b1 = Bs[cb + fr][kk + fc + 4];
                unsigned bh0 = tf32_hi(b0), bh1 = tf32_hi(b1);
                unsigned bl0 = __float_as_uint(b0 - __uint_as_float(bh0));
                unsigned bl1 = __float_as_uint(b1 - __uint_as_float(bh1));
#pragma unroll
                for (int mt = 0; mt < 2; mt++) {
                    mma_tf32(acc[mt][nt], ah[mt][0], ah[mt][1], ah[mt][2], ah[mt][3], bh0, bh1);
                    mma_tf32(acc[mt][nt], ah[mt][0], ah[mt][1], ah[mt][2], ah[mt][3], bl0, bl1);
                    mma_tf32(acc[mt][nt], al[mt][0], al[mt][1], al[mt][2], al[mt][3], bh0, bh1);
                }
            }
        }
        __syncthreads();
    }

    // epilogue: c0/c1 -> (row fr, cols 2fc,2fc+1); c2/c3 -> row fr+8
#pragma unroll
    for (int mt = 0; mt < 2; mt++) {
        int r0 = row0 + warp_m * 32 + mt * 16 + fr;
        int r1 = r0 + 8;
#pragma unroll
        for (int nt = 0; nt < 8; nt++) {
            int n0 = warp_n * 64 + nt * 8 + 2 * fc;
            if (r0 < n_nodes)
                *(float2*)&g_ft[(size_t)r0 * HO + n0] = make_float2(acc[mt][nt][0], acc[mt][nt][1]);
            if (r1 < n_nodes)
                *(float2*)&g_ft[(size_t)r1 * HO + n0] = make_float2(acc[mt][nt][2], acc[mt][nt][3]);
        }
    }
}

// ---------------- kernel 2: el/er per node (warp per node) -----------------
__global__ __launch_bounds__(256) void k_attn_dot(const float* __restrict__ attn,
                                                  int n_nodes) {
    int warp = (blockIdx.x * blockDim.x + threadIdx.x) >> 5;
    int lane = threadIdx.x & 31;
    if (warp >= n_nodes) return;

    float4 f = ((const float4*)g_ft)[(size_t)warp * 32 + lane];
    int h   = lane >> 3;
    int off = (lane & 7) * 4;
    float4 al = *(const float4*)&attn[h * 64 + off];
    float4 ar = *(const float4*)&attn[h * 64 + 32 + off];
    float dl = f.x * al.x + f.y * al.y + f.z * al.z + f.w * al.w;
    float dr = f.x * ar.x + f.y * ar.y + f.z * ar.z + f.w * ar.w;
#pragma unroll
    for (int m = 4; m >= 1; m >>= 1) {
        dl += __shfl_xor_sync(0xffffffffu, dl, m);
        dr += __shfl_xor_sync(0xffffffffu, dr, m);
    }
    if ((lane & 7) == 0) {
        g_el[warp * HEADS + h] = dl;
        g_er[warp * HEADS + h] = dr;
    }
}

// ---------------- kernel 3: degree histogram over dst ----------------------
__global__ __launch_bounds__(256) void k_hist(const void* __restrict__ dst,
                                              int n_edges, int n_nodes) {
    int i = blockIdx.x * blockDim.x + threadIdx.x;
    if (i >= n_edges) return;
    int d = load_idx(dst, i, g_is64, n_nodes);
    atomicAdd(&g_deg[d], 1);
}

// ---------------- kernel 4: single-block exclusive scan --------------------
__global__ __launch_bounds__(1024) void k_scan(int n) {
    __shared__ int wsum[32];
    const int tid  = threadIdx.x;
    const int lane = tid & 31;
    const int wid  = tid >> 5;
    const int per  = (n + 1023) >> 10;
    const int beg  = tid * per;
    const int end  = min(beg + per, n);

    int local = 0;
    for (int j = beg; j < end; j++) local += g_deg[j];

    int v = local;
#pragma unroll
    for (int o = 1; o < 32; o <<= 1) {
        int t = __shfl_up_sync(0xffffffffu, v, o);
        if (lane >= o) v += t;
    }
    if (lane == 31) wsum[wid] = v;
    __syncthreads();
    if (wid == 0) {
        int s = wsum[lane];
#pragma unroll
        for (int o = 1; o < 32; o <<= 1) {
            int t = __shfl_up_sync(0xffffffffu, s, o);
            if (lane >= o) s += t;
        }
        wsum[lane] = s;
    }
    __syncthreads();

    int pre = v - local + (wid > 0 ? wsum[wid - 1] : 0);
    int run = pre;
    for (int j = beg; j < end; j++) {
        int d = g_deg[j];
        g_off[j]    = run;
        g_cursor[j] = run;
        run += d;
    }
    if (beg < n && end == n) g_off[n] = run;
}

// ---------------- kernel 5: scatter edge ids into CSR ----------------------
__global__ __launch_bounds__(256) void k_scatter(const void* __restrict__ dst,
                                                 int n_edges, int n_nodes) {
    int i = blockIdx.x * blockDim.x + threadIdx.x;
    if (i >= n_edges) return;
    int d = load_idx(dst, i, g_is64, n_nodes);
    int pos = atomicAdd(&g_cursor[d], 1);
    g_perm[pos] = i;
}

// ---------------- kernel 6: fused softmax + aggregation (warp per node) ----
__global__ __launch_bounds__(256) void k_agg_csr(const void* __restrict__ src,
                                                 float* __restrict__ out,
                                                 int n_nodes) {
    int node = (blockIdx.x * blockDim.x + threadIdx.x) >> 5;
    int lane = threadIdx.x & 31;
    if (node >= n_nodes) return;

    const int is64 = g_is64;
    const int beg = g_off[node];
    const int end = g_off[node + 1];
    const int h   = lane >> 3;
    const float er_h = g_er[node * HEADS + h];

    float4 acc = make_float4(0.f, 0.f, 0.f, 0.f);
    float  sw  = 0.f;

    int j = beg;
    for (; j + 1 < end; j += 2) {           // 2-edge unroll: 2 gathers in flight
        int e0 = g_perm[j];
        int e1 = g_perm[j + 1];
        int s0 = load_idx(src, e0, is64, n_nodes);
        int s1 = load_idx(src, e1, is64, n_nodes);
        float lg0 = g_el[s0 * HEADS + h] + er_h;
        float lg1 = g_el[s1 * HEADS + h] + er_h;
        lg0 = lg0 > 0.f ? lg0 : NEG_SLOPE * lg0;
        lg1 = lg1 > 0.f ? lg1 : NEG_SLOPE * lg1;
        float w0 = __expf(lg0);
        float w1 = __expf(lg1);
        float4 f0 = ((const float4*)g_ft)[(size_t)s0 * 32 + lane];
        float4 f1 = ((const float4*)g_ft)[(size_t)s1 * 32 + lane];
        acc.x += w0 * f0.x + w1 * f1.x;
        acc.y += w0 * f0.y + w1 * f1.y;
        acc.z += w0 * f0.z + w1 * f1.z;
        acc.w += w0 * f0.w + w1 * f1.w;
        sw += w0 + w1;
    }
    if (j < end) {
        int e0 = g_perm[j];
        int s0 = load_idx(src, e0, is64, n_nodes);
        float lg0 = g_el[s0 * HEADS + h] + er_h;
        lg0 = lg0 > 0.f ? lg0 : NEG_SLOPE * lg0;
        float w0 = __expf(lg0);
        float4 f0 = ((const float4*)g_ft)[(size_t)s0 * 32 + lane];
        acc.x += w0 * f0.x; acc.y += w0 * f0.y;
        acc.z += w0 * f0.z; acc.w += w0 * f0.w;
        sw += w0;
    }

    float inv = sw > 0.f ? __fdividef(1.f, sw) : 0.f;
    ((float4*)out)[(size_t)node * 32 + lane] =
        make_float4(acc.x * inv, acc.y * inv, acc.z * inv, acc.w * inv);
}

// ---------------- launch ---------------------------------------------------
extern "C" void kernel_launch(void* const* d_in, const int* in_sizes, int n_in,
                              void* d_out, int out_size) {
    const float* feat = (const float*)d_in[0];
    const void*  src  = d_in[1];
    const void*  dst  = d_in[2];
    const float* W    = (const float*)d_in[3];
    const float* attn = (const float*)d_in[4];
    float*       out  = (float*)d_out;

    const int n_nodes = in_sizes[0] / FIN;   // 50000
    const int n_edges = in_sizes[1];         // 1600000

    // D) detect index dtype + zero degree histogram
    k_detect<<<(n_nodes + 255) / 256, 256>>>((const unsigned int*)src, n_nodes);
    // 1) GEMM (tf32 tensor, 3xTF32 compensated)
    k_gemm_tc<<<(n_nodes + TBM - 1) / TBM, 256>>>(feat, W, n_nodes);
    // 2) attention dots
    k_attn_dot<<<(n_nodes * 32 + 255) / 256, 256>>>(attn, n_nodes);
    // 3) CSR: histogram
    k_hist<<<(n_edges + 255) / 256, 256>>>(dst, n_edges, n_nodes);
    // 4) CSR: scan
    k_scan<<<1, 1024>>>(n_nodes);
    // 5) CSR: scatter
    k_scatter<<<(n_edges + 255) / 256, 256>>>(dst, n_edges, n_nodes);
    // 6) fused softmax + aggregation
    k_agg_csr<<<(n_nodes * 32 + 255) / 256, 256>>>(src, out, n_nodes);
}